// round 17
// baseline (speedup 1.0000x reference)
#include <cuda_runtime.h>
#include <cuda_bf16.h>
#include <cstdint>

#define NB 8
#define NT 1024
#define ND 512
#define NH 8
#define NDH 64
#define NSPOS 2047
#define ATT_SCALE 0.125f

typedef unsigned long long ull;

// ---------------- scratch (device globals; no allocs allowed) ----------------
__device__ float g_q[NB*NH*NT*NDH];
__device__ float g_v[NB*NH*NT*NDH];
__device__ __nv_bfloat16 g_kh[NB*NH*NT*NDH], g_kl[NB*NH*NT*NDH];
__device__ __nv_bfloat16 g_ph[NH*NSPOS*NDH], g_pl[NH*NSPOS*NDH];
__device__ __nv_bfloat16 g_vth[NB*NH*NDH*NT], g_vtl[NB*NH*NDH*NT];
__device__ __nv_bfloat16 g_xh[NB*NT*ND],  g_xl[NB*NT*ND];
__device__ __nv_bfloat16 g_peh[2048*ND],  g_pel[2048*ND];
__device__ __nv_bfloat16 g_wth[5*ND*ND],  g_wtl[5*ND*ND];
__device__ __nv_bfloat16 g_aoh[NB*NT*ND], g_aol[NB*NT*ND];

// ---------------- mma.sync / ldmatrix / cp.async helpers ----------------
__device__ __forceinline__ uint32_t smem_u32(const void* p) {
    uint32_t a;
    asm("{ .reg .u64 t; cvta.to.shared.u64 t, %1; cvt.u32.u64 %0, t; }" : "=r"(a) : "l"(p));
    return a;
}
#define LDSM4(r, addr) \
    asm volatile("ldmatrix.sync.aligned.m8n8.x4.shared.b16 {%0,%1,%2,%3}, [%4];" \
        : "=r"((r)[0]), "=r"((r)[1]), "=r"((r)[2]), "=r"((r)[3]) : "r"(addr))
#define MMA16816(c, a, b0, b1) \
    asm volatile("mma.sync.aligned.m16n8k16.row.col.f32.bf16.bf16.f32 " \
        "{%0,%1,%2,%3}, {%4,%5,%6,%7}, {%8,%9}, {%0,%1,%2,%3};" \
        : "+f"((c)[0]), "+f"((c)[1]), "+f"((c)[2]), "+f"((c)[3]) \
        : "r"((a)[0]), "r"((a)[1]), "r"((a)[2]), "r"((a)[3]), "r"(b0), "r"(b1))
__device__ __forceinline__ void cpa16(uint32_t dst, const void* src, int sz) {
    asm volatile("cp.async.cg.shared.global [%0], [%1], 16, %2;"
                 :: "r"(dst), "l"(src), "r"(sz) : "memory");
}
__device__ __forceinline__ void cpa16f(uint32_t dst, const void* src) {
    asm volatile("cp.async.cg.shared.global [%0], [%1], 16;"
                 :: "r"(dst), "l"(src) : "memory");
}
__device__ __forceinline__ void cpa_commit() {
    asm volatile("cp.async.commit_group;" ::: "memory");
}
__device__ __forceinline__ void cpa_wait0() {
    asm volatile("cp.async.wait_group 0;" ::: "memory");
}

// split a float4 into hi/lo bf16 quads
__device__ __forceinline__ void split4(float4 v, __nv_bfloat16* hdst, __nv_bfloat16* ldst) {
    __nv_bfloat16 h0 = __float2bfloat16(v.x), h1 = __float2bfloat16(v.y);
    __nv_bfloat16 h2 = __float2bfloat16(v.z), h3 = __float2bfloat16(v.w);
    ((__nv_bfloat162*)hdst)[0] = __nv_bfloat162(h0, h1);
    ((__nv_bfloat162*)hdst)[1] = __nv_bfloat162(h2, h3);
    ((__nv_bfloat162*)ldst)[0] = __nv_bfloat162(
        __float2bfloat16(v.x - __bfloat162float(h0)),
        __float2bfloat16(v.y - __bfloat162float(h1)));
    ((__nv_bfloat162*)ldst)[1] = __nv_bfloat162(
        __float2bfloat16(v.z - __bfloat162float(h2)),
        __float2bfloat16(v.w - __bfloat162float(h3)));
}

// ---------------- split-precision convert kernels ----------------
__global__ __launch_bounds__(256)
void split_k(const float* __restrict__ s, __nv_bfloat16* __restrict__ h,
             __nv_bfloat16* __restrict__ l, int n4)
{
    int i = blockIdx.x * 256 + threadIdx.x;
    if (i >= n4) return;
    float4 v = ((const float4*)s)[i];
    split4(v, h + i * 4, l + i * 4);
}

// Transpose + split the 5 weight matrices: wt[z][n][k] = W_z[k][n]
__global__ __launch_bounds__(256)
void wsplit_k(const float* __restrict__ W0, const float* __restrict__ W1,
              const float* __restrict__ W2, const float* __restrict__ W3,
              const float* __restrict__ W4,
              __nv_bfloat16* __restrict__ th, __nv_bfloat16* __restrict__ tl)
{
    const float* W;
    switch (blockIdx.z) {
        case 0: W = W0; break;
        case 1: W = W1; break;
        case 2: W = W2; break;
        case 3: W = W3; break;
        default: W = W4; break;
    }
    __shared__ float t[32][33];
    int tx = threadIdx.x & 31, ty = threadIdx.x >> 5;
    int n0 = blockIdx.x * 32, k0 = blockIdx.y * 32;
#pragma unroll
    for (int ph = 0; ph < 4; ph++)
        t[ty + ph * 8][tx] = W[(size_t)(k0 + ty + ph * 8) * ND + n0 + tx];
    __syncthreads();
    size_t base = (size_t)blockIdx.z * ND * ND;
#pragma unroll
    for (int ph = 0; ph < 4; ph++) {
        int n = n0 + ty + ph * 8, k = k0 + tx;
        float v = t[tx][ty + ph * 8];
        __nv_bfloat16 hh = __float2bfloat16(v);
        __nv_bfloat16 ll = __float2bfloat16(v - __bfloat162float(hh));
        th[base + (size_t)n * ND + k] = hh;
        tl[base + (size_t)n * ND + k] = ll;
    }
}

// V transpose+split: vt[bh][d][t] (bf16 h/l) from v[bh][t][d] f32.
__global__ __launch_bounds__(256)
void vtrans_k(const float* __restrict__ v,
              __nv_bfloat16* __restrict__ vth, __nv_bfloat16* __restrict__ vtl)
{
    __shared__ float sh[64][65];
    const int tid = threadIdx.x;
    const int bh = blockIdx.y;
    const int t0 = blockIdx.x << 6;
    const float* vb = v + ((size_t)bh * NT + t0) * NDH;
#pragma unroll
    for (int p = 0; p < 4; p++) {
        int e = tid + (p << 8);
        int r = e >> 4, c4 = (e & 15) << 2;
        float4 t = *(const float4*)(vb + r * NDH + c4);
        sh[r][c4+0] = t.x; sh[r][c4+1] = t.y; sh[r][c4+2] = t.z; sh[r][c4+3] = t.w;
    }
    __syncthreads();
    __nv_bfloat16* oh = vth + (size_t)bh * NDH * NT;
    __nv_bfloat16* ol = vtl + (size_t)bh * NDH * NT;
    const int c = tid & 63;
    const int d0 = tid >> 6;
#pragma unroll
    for (int m = 0; m < 16; m++) {
        int d = d0 + (m << 2);
        float val = sh[c][d];
        __nv_bfloat16 hh = __float2bfloat16(val);
        oh[(size_t)d * NT + t0 + c] = hh;
        ol[(size_t)d * NT + t0 + c] = __float2bfloat16(val - __bfloat162float(hh));
    }
}

// ---------------------------------------------------------------------------
// mma.sync split-bf16 GEMM. MODE 0: f32 row-major; MODE 1: f32 [b][h][t][d];
// MODE 3: split bf16 [bh][t][d]; MODE 4: split bf16 [h][j][d].
// ---------------------------------------------------------------------------
#define MT_AH 0
#define MT_AL 10240
#define MT_BH 20480
#define MT_BL 30720
#define MT_BUF 40960
#define MT_SMEM 81920

template<int MODE>
__device__ __forceinline__
void mmagemm_body(const __nv_bfloat16* __restrict__ Ah, const __nv_bfloat16* __restrict__ Al,
                  const __nv_bfloat16* __restrict__ Bh, const __nv_bfloat16* __restrict__ Bl,
                  const float* __restrict__ bias, float* __restrict__ C,
                  __nv_bfloat16* __restrict__ Ch, __nv_bfloat16* __restrict__ Cl,
                  int M, int row0, int col0, char* smraw)
{
    const int tid  = threadIdx.x;
    const int lane = tid & 31;
    const int wid  = tid >> 5;
    const int warp_m = wid >> 2;
    const int warp_n = wid & 3;
    const uint32_t smb = smem_u32(smraw);

    const int ldrow = tid >> 1;
    const int ldc8  = (tid & 1) * 16;
    const bool okA  = (row0 + ldrow) < M;
    const size_t agoff = (size_t)(row0 + ldrow) * ND;
    const size_t bgoff = (size_t)(col0 + ldrow) * ND;
    const uint32_t srow = (uint32_t)ldrow * 40;
    const int szA = okA ? 16 : 0;

    float acc[4][4][4];
#pragma unroll
    for (int mi = 0; mi < 4; mi++)
#pragma unroll
        for (int ni = 0; ni < 4; ni++)
#pragma unroll
            for (int e = 0; e < 4; e++) acc[mi][ni][e] = 0.f;

    const int a_row = warp_m * 64 + (lane & 7) + ((lane >> 3) & 1) * 8;
    const int b_row = warp_n * 32 + (lane & 7) + ((lane >> 3) & 1) * 8;
    const int lm_k  = (lane >> 4) * 8;

    auto load_tile = [&](int k0, int buf) {
        uint32_t sb = smb + buf * MT_BUF;
#pragma unroll
        for (int c = 0; c < 2; c++) {
            int col = ldc8 + c * 8;
            uint32_t so = (srow + col) * 2;
            cpa16(sb + MT_AH + so, Ah + agoff + k0 + col, szA);
            cpa16(sb + MT_AL + so, Al + agoff + k0 + col, szA);
            cpa16(sb + MT_BH + so, Bh + bgoff + k0 + col, 16);
            cpa16(sb + MT_BL + so, Bl + bgoff + k0 + col, 16);
        }
    };

    load_tile(0, 0);
    cpa_commit();

    int buf = 0;
    for (int it = 0; it < 16; it++) {
        cpa_wait0();
        __syncthreads();
        if (it < 15) {
            load_tile((it + 1) * 32, buf ^ 1);
            cpa_commit();
        }
        const uint32_t sb = smb + buf * MT_BUF;
#pragma unroll
        for (int ks = 0; ks < 2; ks++) {
            const int kofs = ks * 16 + lm_k;
            uint32_t bh[2][4], bl[2][4];
#pragma unroll
            for (int p = 0; p < 2; p++) {
                uint32_t off = (uint32_t)((b_row + p * 16) * 40 + kofs) * 2;
                LDSM4(bh[p], sb + MT_BH + off);
                LDSM4(bl[p], sb + MT_BL + off);
            }
#pragma unroll
            for (int mi = 0; mi < 4; mi++) {
                uint32_t ah[4], al[4];
                uint32_t off = (uint32_t)((a_row + mi * 16) * 40 + kofs) * 2;
                LDSM4(ah, sb + MT_AH + off);
                LDSM4(al, sb + MT_AL + off);
#pragma unroll
                for (int ni = 0; ni < 4; ni++) {
                    const int p = ni >> 1, hi = ni & 1;
                    MMA16816(acc[mi][ni], ah, bh[p][hi], bh[p][hi + 2]);
                    MMA16816(acc[mi][ni], ah, bl[p][hi], bl[p][hi + 2]);
                    MMA16816(acc[mi][ni], al, bh[p][hi], bh[p][hi + 2]);
                }
            }
        }
        buf ^= 1;
    }

#pragma unroll
    for (int mi = 0; mi < 4; mi++) {
        const int r0 = row0 + warp_m * 64 + mi * 16 + (lane >> 2);
#pragma unroll
        for (int ni = 0; ni < 4; ni++) {
            const int col = col0 + warp_n * 32 + ni * 8 + (lane & 3) * 2;
            const float b0 = bias ? bias[col] : 0.f;
            const float b1 = bias ? bias[col + 1] : 0.f;
#pragma unroll
            for (int half = 0; half < 2; half++) {
                const int m = r0 + half * 8;
                if (m >= M) continue;
                float ox = acc[mi][ni][half * 2 + 0] + b0;
                float oy = acc[mi][ni][half * 2 + 1] + b1;
                if (MODE == 0) {
                    *(float2*)(C + (size_t)m * ND + col) = make_float2(ox, oy);
                } else if (MODE == 1) {
                    int b = m >> 10, t = m & 1023;
                    int h = col >> 6, d = col & 63;
                    *(float2*)(C + ((size_t)((b << 3) + h) * NT + t) * NDH + d) = make_float2(ox, oy);
                } else if (MODE == 3) {
                    int b = m >> 10, t = m & 1023;
                    int h = col >> 6, d = col & 63;
                    size_t idx = ((size_t)((b << 3) + h) * NT + t) * NDH + d;
                    __nv_bfloat16 h0 = __float2bfloat16(ox);
                    __nv_bfloat16 h1 = __float2bfloat16(oy);
                    *(__nv_bfloat162*)(Ch + idx) = __nv_bfloat162(h0, h1);
                    *(__nv_bfloat162*)(Cl + idx) = __nv_bfloat162(
                        __float2bfloat16(ox - __bfloat162float(h0)),
                        __float2bfloat16(oy - __bfloat162float(h1)));
                } else {
                    int h = col >> 6, d = col & 63;
                    size_t idx = ((size_t)h * NSPOS + m) * NDH + d;
                    __nv_bfloat16 h0 = __float2bfloat16(ox);
                    __nv_bfloat16 h1 = __float2bfloat16(oy);
                    *(__nv_bfloat162*)(Ch + idx) = __nv_bfloat162(h0, h1);
                    *(__nv_bfloat162*)(Cl + idx) = __nv_bfloat162(
                        __float2bfloat16(ox - __bfloat162float(h0)),
                        __float2bfloat16(oy - __bfloat162float(h1)));
                }
            }
        }
    }
}

template<int MODE>
__global__ __launch_bounds__(256, 2)
void mmagemm_k(const __nv_bfloat16* __restrict__ Ah, const __nv_bfloat16* __restrict__ Al,
               const __nv_bfloat16* __restrict__ Bh, const __nv_bfloat16* __restrict__ Bl,
               const float* __restrict__ bias, float* __restrict__ C, int M)
{
    extern __shared__ char smraw[];
    mmagemm_body<MODE>(Ah, Al, Bh, Bl, bias, C, nullptr, nullptr, M,
                       blockIdx.x << 7, blockIdx.y << 7, smraw);
}

__global__ __launch_bounds__(256, 2)
void mmagemm_fused_k(const __nv_bfloat16* __restrict__ xh, const __nv_bfloat16* __restrict__ xl,
                     const __nv_bfloat16* __restrict__ peh, const __nv_bfloat16* __restrict__ pel,
                     const __nv_bfloat16* __restrict__ wth, const __nv_bfloat16* __restrict__ wtl,
                     const float* __restrict__ bq, const float* __restrict__ bk,
                     const float* __restrict__ bv,
                     float* __restrict__ Cq, float* __restrict__ Cv,
                     __nv_bfloat16* __restrict__ kh, __nv_bfloat16* __restrict__ kl,
                     __nv_bfloat16* __restrict__ ph, __nv_bfloat16* __restrict__ pl)
{
    extern __shared__ char smraw[];
    const int z = blockIdx.z;
    const size_t WSZ = (size_t)ND * ND;
    const int r0 = blockIdx.x << 7, c0 = blockIdx.y << 7;
    if (z == 0) {
        mmagemm_body<1>(xh, xl, wth, wtl, bq, Cq, nullptr, nullptr, NB * NT, r0, c0, smraw);
    } else if (z == 1) {
        mmagemm_body<3>(xh, xl, wth + WSZ, wtl + WSZ, bk, nullptr, kh, kl, NB * NT, r0, c0, smraw);
    } else if (z == 2) {
        mmagemm_body<1>(xh, xl, wth + 2 * WSZ, wtl + 2 * WSZ, bv, Cv, nullptr, nullptr, NB * NT, r0, c0, smraw);
    } else {
        if (blockIdx.x >= 16) return;
        mmagemm_body<4>(peh, pel, wth + 3 * WSZ, wtl + 3 * WSZ, nullptr, nullptr, ph, pl, NSPOS, r0, c0, smraw);
    }
}

// ---------------------------------------------------------------------------
// attn_k v5: all staging via cp.async of pre-split bf16 (K, P, Vt); content,
// pos (smem ring) and AV on tensor pipe. 64q x 64k tiles, 256 thr, pipelined.
// ---------------------------------------------------------------------------
#define AT_QUH 0
#define AT_QUL 9216
#define AT_QVH 18432
#define AT_QVL 27648
#define AT_KH  36864
#define AT_KL  46080
#define AT_VT  55296    // 2 buffers x 18432 (H +0, L +9216)
#define AT_PE  92160    // 2 buffers x 18432 (H +0, L +9216)
#define AT_PRH 129024
#define AT_PRL 138240
#define AT_RING 147456  // f32 [64][132]
#define AT_SS   181248  // f32 [64][66]
#define AT_ALPHA 198144 // f32 [64]
#define AT_SL    198400 // f32 [64]
#define AT_SMEM  198656

__global__ __launch_bounds__(256)
void attn_k(const float* __restrict__ q,
            const __nv_bfloat16* __restrict__ kh, const __nv_bfloat16* __restrict__ kl,
            const __nv_bfloat16* __restrict__ vth, const __nv_bfloat16* __restrict__ vtl,
            const __nv_bfloat16* __restrict__ ph, const __nv_bfloat16* __restrict__ pl,
            const float* __restrict__ pbu, const float* __restrict__ pbv,
            __nv_bfloat16* __restrict__ aoh, __nv_bfloat16* __restrict__ aol)
{
    extern __shared__ char smraw[];
    const uint32_t smb = smem_u32(smraw);
    __nv_bfloat16* sm16 = (__nv_bfloat16*)smraw;
    float* ring   = (float*)(smraw + AT_RING);
    float* sS     = (float*)(smraw + AT_SS);
    float* salpha = (float*)(smraw + AT_ALPHA);
    float* sl     = (float*)(smraw + AT_SL);
    __nv_bfloat16* prh = sm16 + AT_PRH / 2;
    __nv_bfloat16* prl = sm16 + AT_PRL / 2;

    const int tid = threadIdx.x;
    const int lane = tid & 31, wid = tid >> 5;
    const int warp_m = wid & 3, warp_n = wid >> 2;
    const int tx = tid >> 4, ty = tid & 15;
    const int bx = blockIdx.x;
    const int t0 = (bx & 15) << 6;
    const int bh = bx >> 4;
    const int h = bh & 7, b = bh >> 3;

    const float* qb = q + ((size_t)bh * NT + t0) * NDH;
    const __nv_bfloat16* khb = kh + (size_t)bh * NT * NDH;
    const __nv_bfloat16* klb = kl + (size_t)bh * NT * NDH;
    const __nv_bfloat16* vthb = vth + (size_t)bh * NDH * NT;
    const __nv_bfloat16* vtlb = vtl + (size_t)bh * NDH * NT;
    const __nv_bfloat16* phb = ph + (size_t)h * NSPOS * NDH;
    const __nv_bfloat16* plb = pl + (size_t)h * NSPOS * NDH;
    const int pj0 = 960 - t0;

    const int a_row = warp_m * 16 + (lane & 7) + 8 * ((lane >> 3) & 1);
    const int b_row = warp_n * 32 + (lane & 7) + 8 * ((lane >> 3) & 1);
    const int lm_k  = (lane >> 4) * 8;
    const int fs_row = warp_m * 16 + (lane >> 2);
    const int fs_col = warp_n * 32 + (lane & 3) * 2;

    // staging maps
    const int ldr = tid >> 2;            // 0..63 (f32 q staging)
    const int ldd = (tid & 3) << 4;
    const int crow = tid >> 3;           // 0..31 (cp.async: 2 passes of rows)
    const int cch  = tid & 7;            // chunk within row (16B)

    // ---- stage Qu/Qv once (f32 + bias add + split) ----
#pragma unroll
    for (int c = 0; c < 4; c++) {
        int d = ldd + c * 4;
        float4 qq = *(const float4*)(qb + ldr * NDH + d);
        float4 uu = *(const float4*)(pbu + h * NDH + d);
        float4 vv = *(const float4*)(pbv + h * NDH + d);
        float4 qu = make_float4(qq.x+uu.x, qq.y+uu.y, qq.z+uu.z, qq.w+uu.w);
        float4 qv = make_float4(qq.x+vv.x, qq.y+vv.y, qq.z+vv.z, qq.w+vv.w);
        int ofs = ldr * 72 + d;
        split4(qu, sm16 + AT_QUH/2 + ofs, sm16 + AT_QUL/2 + ofs);
        split4(qv, sm16 + AT_QVH/2 + ofs, sm16 + AT_QVL/2 + ofs);
    }

    auto cpa_k = [&](int n) {
#pragma unroll
        for (int p = 0; p < 2; p++) {
            int row = crow + p * 32;
            uint32_t so = (uint32_t)row * 144 + cch * 16;
            size_t go = (size_t)(n * 64 + row) * NDH + cch * 8;
            cpa16f(smb + AT_KH + so, khb + go);
            cpa16f(smb + AT_KL + so, klb + go);
        }
    };
    auto cpa_v = [&](int n, int buf) {
        uint32_t sb = smb + AT_VT + buf * 18432;
#pragma unroll
        for (int p = 0; p < 2; p++) {
            int d = crow + p * 32;
            uint32_t so = (uint32_t)d * 144 + cch * 16;
            size_t go = (size_t)d * NT + n * 64 + cch * 8;
            cpa16f(sb + so, vthb + go);
            cpa16f(sb + 9216 + so, vtlb + go);
        }
    };
    auto cpa_pe = [&](int blk) {
        uint32_t sb = smb + AT_PE + (blk & 1) * 18432;
#pragma unroll
        for (int p = 0; p < 2; p++) {
            int row = crow + p * 32;
            int j = pj0 + blk * 64 + row;
            j = j > 2046 ? 2046 : j;
            uint32_t so = (uint32_t)row * 144 + cch * 16;
            size_t go = (size_t)j * NDH + cch * 8;
            cpa16f(sb + so, phb + go);
            cpa16f(sb + 9216 + so, plb + go);
        }
    };

    // generic 64x64x64 split MMA (3 products) into fresh cc
    auto mma_tile = [&](uint32_t aH, uint32_t aL, uint32_t bH, uint32_t bL,
                        float cc[4][4]) {
#pragma unroll
        for (int ni = 0; ni < 4; ni++)
#pragma unroll
            for (int e = 0; e < 4; e++) cc[ni][e] = 0.f;
#pragma unroll
        for (int ks = 0; ks < 4; ks++) {
            const int kofs = ks * 16 + lm_k;
            uint32_t ah[4], al[4], bh2[2][4], bl2[2][4];
            LDSM4(ah, aH + (uint32_t)(a_row * 72 + kofs) * 2);
            LDSM4(al, aL + (uint32_t)(a_row * 72 + kofs) * 2);
#pragma unroll
            for (int p2 = 0; p2 < 2; p2++) {
                uint32_t off = (uint32_t)((b_row + p2 * 16) * 72 + kofs) * 2;
                LDSM4(bh2[p2], bH + off);
                LDSM4(bl2[p2], bL + off);
            }
#pragma unroll
            for (int ni = 0; ni < 4; ni++) {
                const int p2 = ni >> 1, hi = ni & 1;
                MMA16816(cc[ni], ah, bh2[p2][hi], bh2[p2][hi + 2]);
                MMA16816(cc[ni], ah, bl2[p2][hi], bl2[p2][hi + 2]);
                MMA16816(cc[ni], al, bh2[p2][hi], bh2[p2][hi + 2]);
            }
        }
    };

    auto pos_mma = [&](int blk) {
        uint32_t pe = smb + AT_PE + (blk & 1) * 18432;
        float cc[4][4];
        mma_tile(smb + AT_QVH, smb + AT_QVL, pe, pe + 9216, cc);
        const int slot = (blk & 1) << 6;
#pragma unroll
        for (int ni = 0; ni < 4; ni++) {
            int col = slot + fs_col + ni * 8;
            *(float2*)(ring + fs_row * 132 + col)       = make_float2(cc[ni][0], cc[ni][1]);
            *(float2*)(ring + (fs_row + 8) * 132 + col) = make_float2(cc[ni][2], cc[ni][3]);
        }
    };

    // ---- preamble ----
    cpa_pe(0); cpa_pe(1); cpa_k(0); cpa_v(0, 0);
    cpa_commit();
    cpa_wait0();
    __syncthreads();
    pos_mma(0);
    pos_mma(1);
    __syncthreads();
    cpa_pe(2);
    cpa_commit();

    float acc_o[4][4];
#pragma unroll
    for (int ni = 0; ni < 4; ni++)
#pragma unroll
        for (int e = 0; e < 4; e++) acc_o[ni][e] = 0.f;
    float m_i[4], l_i[4];
#pragma unroll
    for (int i = 0; i < 4; i++) { m_i[i] = -3.0e38f; l_i[i] = 0.f; }

    for (int n = 0; n < 16; n++) {
        // ---- content score MMA -> sS ----
        {
            float cc[4][4];
            mma_tile(smb + AT_QUH, smb + AT_QUL, smb + AT_KH, smb + AT_KL, cc);
#pragma unroll
            for (int ni = 0; ni < 4; ni++) {
                int col = fs_col + ni * 8;
                *(float2*)(sS + fs_row * 66 + col)       = make_float2(cc[ni][0], cc[ni][1]);
                *(float2*)(sS + (fs_row + 8) * 66 + col) = make_float2(cc[ni][2], cc[ni][3]);
            }
        }
        __syncthreads();
        // ---- issue next-tile cp.async (single commit point per iter) ----
        if (n < 15) { cpa_k(n + 1); cpa_v(n + 1, (n + 1) & 1); }
        if (n + 3 <= 16) cpa_pe(n + 3);
        cpa_commit();

        // ---- softmax: split-bf16 P + alpha ----
        const int pw = (n << 6) + 63;
#pragma unroll
        for (int i = 0; i < 4; i++) {
            const int r = tx + (i << 4);
            float s[4];
            float mt = -3.0e38f;
#pragma unroll
            for (int j = 0; j < 4; j++) {
                const int c = ty + (j << 4);
                const int rc = (pw + c - r) & 127;
                s[j] = (sS[r * 66 + c] + ring[r * 132 + rc]) * ATT_SCALE;
                mt = fmaxf(mt, s[j]);
            }
#pragma unroll
            for (int off = 8; off >= 1; off >>= 1)
                mt = fmaxf(mt, __shfl_xor_sync(0xffffffffu, mt, off));
            float mn = fmaxf(m_i[i], mt);
            float alpha = __expf(m_i[i] - mn);
            m_i[i] = mn;
            float rs = 0.f;
#pragma unroll
            for (int j = 0; j < 4; j++) {
                float ev = __expf(s[j] - mn);
                s[j] = ev;
                rs += ev;
            }
#pragma unroll
            for (int off = 8; off >= 1; off >>= 1)
                rs += __shfl_xor_sync(0xffffffffu, rs, off);
            l_i[i] = l_i[i] * alpha + rs;
            if (ty == 0) salpha[r] = alpha;
#pragma unroll
            for (int j = 0; j < 4; j++) {
                const int c = ty + (j << 4);
                __nv_bfloat16 hh = __float2bfloat16(s[j]);
                prh[r * 72 + c] = hh;
                prl[r * 72 + c] = __float2bfloat16(s[j] - __bfloat162float(hh));
            }
        }
        __syncthreads();

        // ---- AV MMA: rescale + accumulate P @ Vt ----
        {
            uint32_t vt = smb + AT_VT + (n & 1) * 18432;
            float a_lo = salpha[fs_row], a_hi = salpha[fs_row + 8];
#pragma unroll
            for (int ni = 0; ni < 4; ni++) {
                acc_o[ni][0] *= a_lo; acc_o[ni][1] *= a_lo;
                acc_o[ni][2] *= a_hi; acc_o[ni][3] *= a_hi;
            }
#pragma unroll
            for (int ks = 0; ks < 4; ks++) {
                const int kofs = ks * 16 + lm_k;
                uint32_t ah[4], al[4], bh2[2][4], bl2[2][4];
                LDSM4(ah, smb + AT_PRH + (uint32_t)(a_row * 72 + kofs) * 2);
                LDSM4(al, smb + AT_PRL + (uint32_t)(a_row * 72 + kofs) * 2);
#pragma unroll
                for (int p2 = 0; p2 < 2; p2++) {
                    uint32_t off = (uint32_t)((b_row + p2 * 16) * 72 + kofs) * 2;
                    LDSM4(bh2[p2], vt + off);
                    LDSM4(bl2[p2], vt + 9216 + off);
                }
#pragma unroll
                for (int ni = 0; ni < 4; ni++) {
                    const int p2 = ni >> 1, hi = ni & 1;
                    MMA16816(acc_o[ni], ah, bh2[p2][hi], bh2[p2][hi + 2]);
                    MMA16816(acc_o[ni], ah, bl2[p2][hi], bl2[p2][hi + 2]);
                    MMA16816(acc_o[ni], al, bh2[p2][hi], bh2[p2][hi + 2]);
                }
            }
        }
        // ---- wait staged tiles, then append ring ----
        cpa_wait0();
        __syncthreads();
        if (n + 2 <= 16) pos_mma(n + 2);
    }

    // ---- epilogue ----
    if (ty == 0) {
#pragma unroll
        for (int i = 0; i < 4; i++) sl[tx + (i << 4)] = l_i[i];
    }
    __syncthreads();
#pragma unroll
    for (int half = 0; half < 2; half++) {
        const int row = fs_row + half * 8;
        const float inv = 1.f / sl[row];
        size_t base = ((size_t)b * NT + t0 + row) * ND + h * NDH;
#pragma unroll
        for (int ni = 0; ni < 4; ni++) {
            const int col = fs_col + ni * 8;
            float o0 = acc_o[ni][half * 2 + 0] * inv;
            float o1 = acc_o[ni][half * 2 + 1] * inv;
            __nv_bfloat16 h0 = __float2bfloat16(o0);
            __nv_bfloat16 h1 = __float2bfloat16(o1);
            *(__nv_bfloat162*)(aoh + base + col) = __nv_bfloat162(h0, h1);
            *(__nv_bfloat162*)(aol + base + col) = __nv_bfloat162(
                __float2bfloat16(o0 - __bfloat162float(h0)),
                __float2bfloat16(o1 - __bfloat162float(h1)));
        }
    }
}

// ---------------------------------------------------------------------------
extern "C" void kernel_launch(void* const* d_in, const int* in_sizes, int n_in,
                              void* d_out, int out_size)
{
    const float* x    = (const float*)d_in[0];
    const float* pe   = (const float*)d_in[1];
    const float* Wq   = (const float*)d_in[2];
    const float* bq   = (const float*)d_in[3];
    const float* Wk   = (const float*)d_in[4];
    const float* bk   = (const float*)d_in[5];
    const float* Wv   = (const float*)d_in[6];
    const float* bv   = (const float*)d_in[7];
    const float* Wpos = (const float*)d_in[8];
    const float* pbu  = (const float*)d_in[9];
    const float* pbv  = (const float*)d_in[10];
    const float* Wo   = (const float*)d_in[11];
    const float* bo   = (const float*)d_in[12];
    float* out = (float*)d_out;

    float *qp, *vp_;
    cudaGetSymbolAddress((void**)&qp,  g_q);
    cudaGetSymbolAddress((void**)&vp_, g_v);
    __nv_bfloat16 *khp, *klp, *php, *plp, *vthp, *vtlp;
    cudaGetSymbolAddress((void**)&khp, g_kh);
    cudaGetSymbolAddress((void**)&klp, g_kl);
    cudaGetSymbolAddress((void**)&php, g_ph);
    cudaGetSymbolAddress((void**)&plp, g_pl);
    cudaGetSymbolAddress((void**)&vthp, g_vth);
    cudaGetSymbolAddress((void**)&vtlp, g_vtl);
    __nv_bfloat16 *xh, *xl, *peh, *pel, *wth, *wtl, *aoh, *aol;
    cudaGetSymbolAddress((void**)&xh,  g_xh);
    cudaGetSymbolAddress((void**)&xl,  g_xl);
    cudaGetSymbolAddress((void**)&peh, g_peh);
    cudaGetSymbolAddress((void**)&pel, g_pel);
    cudaGetSymbolAddress((void**)&wth, g_wth);
    cudaGetSymbolAddress((void**)&wtl, g_wtl);
    cudaGetSymbolAddress((void**)&aoh, g_aoh);
    cudaGetSymbolAddress((void**)&aol, g_aol);

    cudaFuncSetAttribute(mmagemm_fused_k, cudaFuncAttributeMaxDynamicSharedMemorySize, MT_SMEM);
    cudaFuncSetAttribute(mmagemm_k<0>,    cudaFuncAttributeMaxDynamicSharedMemorySize, MT_SMEM);
    cudaFuncSetAttribute(attn_k,          cudaFuncAttributeMaxDynamicSharedMemorySize, AT_SMEM);

    const size_t WSZ = (size_t)ND * ND;
    dim3 blk(256);

    split_k<<<(NB*NT*ND/4 + 255)/256, blk>>>(x,  xh,  xl,  NB*NT*ND/4);
    split_k<<<(NSPOS*ND/4 + 255)/256, blk>>>(pe, peh, pel, NSPOS*ND/4);
    wsplit_k<<<dim3(16, 16, 5), blk>>>(Wq, Wk, Wv, Wpos, Wo, wth, wtl);

    mmagemm_fused_k<<<dim3(64, 4, 4), blk, MT_SMEM>>>(xh, xl, peh, pel, wth, wtl,
                                                      bq, bk, bv, qp, vp_,
                                                      khp, klp, php, plp);
    vtrans_k<<<dim3(16, 64), blk>>>(vp_, vthp, vtlp);
    attn_k<<<NB * NH * (NT / 64), blk, AT_SMEM>>>(qp, khp, klp, vthp, vtlp,
                                                  php, plp, pbu, pbv, aoh, aol);
    mmagemm_k<0><<<dim3(64, 4), blk, MT_SMEM>>>(aoh, aol, wth + 4*WSZ, wtl + 4*WSZ,
                                                bo, out, NB * NT);
}